// round 2
// baseline (speedup 1.0000x reference)
#include <cuda_runtime.h>

// ---------------- scratch (no cudaMalloc allowed) ----------------
__device__ float g_qw[4u * 1024u * 1024u];
__device__ float g_kw[4u * 1024u * 1024u];
__device__ float g_vw[4u * 1024u * 1024u];
__device__ float g_att[4u * 1024u * 1024u];

// ---------------- SGEMM: C = A[MxK] * W[KxN] + bias, optional qmask row scale
// BM=BN=128, BK=16, 256 threads, 8x8 per-thread micro-tile.
__global__ void __launch_bounds__(256) sgemm_bias_kernel(
    const float* __restrict__ A, const float* __restrict__ W,
    const float* __restrict__ bias, const int* __restrict__ qmask,
    float* __restrict__ C, int M, int N, int K, int applyQmask)
{
    __shared__ float As[16][132];   // [k][m], padded
    __shared__ float Bs[16][128];   // [k][n]

    const int bx = blockIdx.x, by = blockIdx.y;
    const int tid = threadIdx.x;
    const int tx = tid & 15, ty = tid >> 4;

    const float* Ablk = A + (size_t)by * 128 * K;
    const float* Bblk = W + (size_t)bx * 128;

    float acc[8][8] = {};

    const int arow = tid >> 2, acol4 = tid & 3;   // A tile: 128x16
    const int brow = tid >> 5, bcol4 = tid & 31;  // W tile: 16x128

    for (int k0 = 0; k0 < K; k0 += 16) {
        #pragma unroll
        for (int p = 0; p < 2; p++) {
            int r = arow + p * 64;
            float4 v = *(const float4*)(Ablk + (size_t)r * K + k0 + acol4 * 4);
            As[acol4 * 4 + 0][r] = v.x;
            As[acol4 * 4 + 1][r] = v.y;
            As[acol4 * 4 + 2][r] = v.z;
            As[acol4 * 4 + 3][r] = v.w;
        }
        #pragma unroll
        for (int p = 0; p < 2; p++) {
            int r = brow + p * 8;
            *(float4*)(&Bs[r][bcol4 * 4]) =
                *(const float4*)(Bblk + (size_t)(k0 + r) * N + bcol4 * 4);
        }
        __syncthreads();

        #pragma unroll
        for (int kk = 0; kk < 16; kk++) {
            float ra[8], rb[8];
            #pragma unroll
            for (int i = 0; i < 8; i++) ra[i] = As[kk][ty * 8 + i];
            #pragma unroll
            for (int j = 0; j < 8; j++) rb[j] = Bs[kk][tx * 8 + j];
            #pragma unroll
            for (int i = 0; i < 8; i++)
                #pragma unroll
                for (int j = 0; j < 8; j++)
                    acc[i][j] += ra[i] * rb[j];
        }
        __syncthreads();
    }

    const int cb = bx * 128 + tx * 8;
    #pragma unroll
    for (int i = 0; i < 8; i++) {
        int row = by * 128 + ty * 8 + i;
        float qm = applyQmask ? (float)qmask[row] : 1.0f;
        float4 v0, v1;
        v0.x = (acc[i][0] + bias[cb + 0]) * qm;
        v0.y = (acc[i][1] + bias[cb + 1]) * qm;
        v0.z = (acc[i][2] + bias[cb + 2]) * qm;
        v0.w = (acc[i][3] + bias[cb + 3]) * qm;
        v1.x = (acc[i][4] + bias[cb + 4]) * qm;
        v1.y = (acc[i][5] + bias[cb + 5]) * qm;
        v1.z = (acc[i][6] + bias[cb + 6]) * qm;
        v1.w = (acc[i][7] + bias[cb + 7]) * qm;
        *(float4*)(&C[(size_t)row * N + cb])     = v0;
        *(float4*)(&C[(size_t)row * N + cb + 4]) = v1;
    }
}

// ---------------- attention kernel ----------------
// One block per (q-tile of 64 rows, b*h). 256 threads.
// Iterates over ALL 16 kv tiles (causal handled additively with -1e12 so the
// reference's exact fp32 tie-breaking for fully-masked rows is reproduced).
__global__ void __launch_bounds__(256) attn_kernel(
    const float* __restrict__ Qg, const float* __restrict__ Kg,
    const float* __restrict__ Vg, const int* __restrict__ vmask,
    float* __restrict__ Og)
{
    extern __shared__ float sm[];
    float* Qt     = sm;               // [64 d][68]  transposed Q tile
    float* Kt     = Qt + 64 * 68;     // [64 d][68]  transposed K tile
    float* Vs     = Kt + 64 * 68;     // [64 kv][68] V tile
    float* Sc     = Vs + 64 * 68;     // [64 row][68] scores / probs
    float* rowm   = Sc + 64 * 68;     // [64]
    float* rowl   = rowm + 64;        // [64]
    float* rowfac = rowl + 64;        // [64]
    float* vmadd  = rowfac + 64;      // [64]

    const int S = 1024, E = 1024;
    const int it  = blockIdx.x;
    const int bh  = blockIdx.y;
    const int b   = bh >> 4, h = bh & 15;
    const int tid = threadIdx.x;
    const int tx  = tid & 15, ty = tid >> 4;

    // load Q tile transposed: Qt[d][r]
    {
        int r0 = tid >> 4, d4 = tid & 15;
        const float* qbase = Qg + ((size_t)(b * S + it * 64)) * E + h * 64;
        #pragma unroll
        for (int p = 0; p < 4; p++) {
            int r = r0 + p * 16;
            float4 v = *(const float4*)(qbase + (size_t)r * E + d4 * 4);
            Qt[(d4 * 4 + 0) * 68 + r] = v.x;
            Qt[(d4 * 4 + 1) * 68 + r] = v.y;
            Qt[(d4 * 4 + 2) * 68 + r] = v.z;
            Qt[(d4 * 4 + 3) * 68 + r] = v.w;
        }
    }
    if (tid < 64) { rowm[tid] = -3.0e38f; rowl[tid] = 0.0f; }

    float oacc[4][4] = {};

    for (int jt = 0; jt < 16; jt++) {
        __syncthreads();  // protect Kt/Vs/Sc from previous iteration readers
        {
            int r0 = tid >> 4, d4 = tid & 15;
            const float* kbase = Kg + ((size_t)(b * S + jt * 64)) * E + h * 64;
            const float* vbase = Vg + ((size_t)(b * S + jt * 64)) * E + h * 64;
            #pragma unroll
            for (int p = 0; p < 4; p++) {
                int r = r0 + p * 16;
                float4 kv = *(const float4*)(kbase + (size_t)r * E + d4 * 4);
                Kt[(d4 * 4 + 0) * 68 + r] = kv.x;
                Kt[(d4 * 4 + 1) * 68 + r] = kv.y;
                Kt[(d4 * 4 + 2) * 68 + r] = kv.z;
                Kt[(d4 * 4 + 3) * 68 + r] = kv.w;
                float4 vv = *(const float4*)(vbase + (size_t)r * E + d4 * 4);
                *(float4*)(&Vs[r * 68 + d4 * 4]) = vv;
            }
            if (tid < 64)
                vmadd[tid] = vmask[b * S + jt * 64 + tid] ? 0.0f : -1.0e12f;
        }
        __syncthreads();

        // scores: 4x4 per thread. rows ty*4.., cols tx*4..
        float sc[4][4] = {};
        #pragma unroll 4
        for (int kk = 0; kk < 64; kk++) {
            float ra[4], rb[4];
            #pragma unroll
            for (int i = 0; i < 4; i++) ra[i] = Qt[kk * 68 + ty * 4 + i];
            #pragma unroll
            for (int j = 0; j < 4; j++) rb[j] = Kt[kk * 68 + tx * 4 + j];
            #pragma unroll
            for (int i = 0; i < 4; i++)
                #pragma unroll
                for (int j = 0; j < 4; j++)
                    sc[i][j] += ra[i] * rb[j];
        }
        #pragma unroll
        for (int i = 0; i < 4; i++) {
            int gr = it * 64 + ty * 4 + i;
            #pragma unroll
            for (int j = 0; j < 4; j++) {
                int gc = jt * 64 + tx * 4 + j;
                float val = sc[i][j] * 0.125f + vmadd[tx * 4 + j];
                if (gc > gr) val += -1.0e12f;   // causal (additive, like ref)
                Sc[(ty * 4 + i) * 68 + tx * 4 + j] = val;
            }
        }
        __syncthreads();

        // online softmax update: 4 lanes per row, 16 cols each
        {
            int row = tid >> 2, sub = tid & 3;
            float lm = -3.0e38f;
            #pragma unroll
            for (int c = 0; c < 16; c++)
                lm = fmaxf(lm, Sc[row * 68 + sub * 16 + c]);
            lm = fmaxf(lm, __shfl_xor_sync(0xffffffffu, lm, 1));
            lm = fmaxf(lm, __shfl_xor_sync(0xffffffffu, lm, 2));
            float mold = rowm[row];
            float mnew = fmaxf(mold, lm);
            float ls = 0.0f;
            #pragma unroll
            for (int c = 0; c < 16; c++) {
                float p = __expf(Sc[row * 68 + sub * 16 + c] - mnew);
                Sc[row * 68 + sub * 16 + c] = p;
                ls += p;
            }
            ls += __shfl_xor_sync(0xffffffffu, ls, 1);
            ls += __shfl_xor_sync(0xffffffffu, ls, 2);
            if (sub == 0) {
                rowfac[row] = __expf(mold - mnew);
                rowl[row]   = rowl[row] * __expf(mold - mnew) + ls;
                rowm[row]   = mnew;
            }
        }
        __syncthreads();

        // rescale accumulator, then O += P * V
        #pragma unroll
        for (int i = 0; i < 4; i++) {
            float f = rowfac[ty * 4 + i];
            #pragma unroll
            for (int j = 0; j < 4; j++) oacc[i][j] *= f;
        }
        #pragma unroll 4
        for (int kk = 0; kk < 64; kk++) {
            float pa[4], vb[4];
            #pragma unroll
            for (int i = 0; i < 4; i++) pa[i] = Sc[(ty * 4 + i) * 68 + kk];
            #pragma unroll
            for (int j = 0; j < 4; j++) vb[j] = Vs[kk * 68 + tx * 4 + j];
            #pragma unroll
            for (int i = 0; i < 4; i++)
                #pragma unroll
                for (int j = 0; j < 4; j++)
                    oacc[i][j] += pa[i] * vb[j];
        }
    }
    __syncthreads();

    #pragma unroll
    for (int i = 0; i < 4; i++) {
        int r = ty * 4 + i;
        float inv = 1.0f / rowl[r];
        size_t orow = ((size_t)(b * S + it * 64 + r)) * E + h * 64;
        #pragma unroll
        for (int j = 0; j < 4; j++)
            Og[orow + tx * 4 + j] = oacc[i][j] * inv;
    }
}

// ---------------- launch ----------------
extern "C" void kernel_launch(void* const* d_in, const int* in_sizes, int n_in,
                              void* d_out, int out_size)
{
    const float* q     = (const float*)d_in[0];
    const float* k     = (const float*)d_in[1];
    const float* v     = (const float*)d_in[2];
    const int*   vmask = (const int*)d_in[3];
    const int*   qmask = (const int*)d_in[4];
    // d_in[5] = a_mask (causal tril; computed from indices instead)
    const float* Wq = (const float*)d_in[6];
    const float* bq = (const float*)d_in[7];
    const float* Wk = (const float*)d_in[8];
    const float* bk = (const float*)d_in[9];
    const float* Wv = (const float*)d_in[10];
    const float* bv = (const float*)d_in[11];
    const float* Wo = (const float*)d_in[12];
    const float* bo = (const float*)d_in[13];
    float* out = (float*)d_out;

    float *qw, *kw, *vw, *att;
    cudaGetSymbolAddress((void**)&qw,  g_qw);
    cudaGetSymbolAddress((void**)&kw,  g_kw);
    cudaGetSymbolAddress((void**)&vw,  g_vw);
    cudaGetSymbolAddress((void**)&att, g_att);

    const int M = 4096, N = 1024, K = 1024;
    dim3 gg(N / 128, M / 128);   // (8, 32)

    sgemm_bias_kernel<<<gg, 256>>>(q, Wq, bq, nullptr, qw, M, N, K, 0);
    sgemm_bias_kernel<<<gg, 256>>>(k, Wk, bk, nullptr, kw, M, N, K, 0);
    sgemm_bias_kernel<<<gg, 256>>>(v, Wv, bv, nullptr, vw, M, N, K, 0);

    const int SMEM_BYTES = (4 * 64 * 68 + 4 * 64) * (int)sizeof(float);  // 70,656 B
    cudaFuncSetAttribute(attn_kernel,
                         cudaFuncAttributeMaxDynamicSharedMemorySize, SMEM_BYTES);
    attn_kernel<<<dim3(16, 64), 256, SMEM_BYTES>>>(qw, kw, vw, vmask, att);

    sgemm_bias_kernel<<<gg, 256>>>(att, Wo, bo, qmask, out, M, N, K, 1);
}

// round 4
// speedup vs baseline: 1.4208x; 1.4208x over previous
#include <cuda_runtime.h>
#include <cuda_bf16.h>
#include <cstdint>

// ==================== scratch (no cudaMalloc allowed) ====================
__device__ float g_qw[4194304];
__device__ float g_kw[4194304];
__device__ float g_vw[4194304];
__device__ float g_att[4194304];
__device__ __nv_bfloat16 g_qh[4194304], g_ql[4194304];
__device__ __nv_bfloat16 g_kh[4194304], g_kl[4194304];
__device__ __nv_bfloat16 g_vh[4194304], g_vl[4194304];
__device__ __nv_bfloat16 g_ah[4194304], g_al[4194304];
__device__ __nv_bfloat16 g_wqh[1048576], g_wql[1048576];
__device__ __nv_bfloat16 g_wkh[1048576], g_wkl[1048576];
__device__ __nv_bfloat16 g_wvh[1048576], g_wvl[1048576];
__device__ __nv_bfloat16 g_woh[1048576], g_wol[1048576];

// ==================== helpers ====================
__device__ __forceinline__ uint32_t smem_u32(const void* p) {
    uint32_t a;
    asm("{ .reg .u64 t; cvta.to.shared.u64 t, %1; cvt.u32.u64 %0, t; }"
        : "=r"(a) : "l"(p));
    return a;
}
__device__ __forceinline__ void cp16(uint32_t s, const void* g) {
    asm volatile("cp.async.cg.shared.global [%0], [%1], 16;" :: "r"(s), "l"(g));
}
#define CP_COMMIT() asm volatile("cp.async.commit_group;" ::: "memory")

__device__ __forceinline__ void ldsm4(uint32_t& r0, uint32_t& r1,
                                      uint32_t& r2, uint32_t& r3, uint32_t a) {
    asm volatile("ldmatrix.sync.aligned.m8n8.x4.shared.b16 {%0,%1,%2,%3}, [%4];"
                 : "=r"(r0), "=r"(r1), "=r"(r2), "=r"(r3) : "r"(a));
}
__device__ __forceinline__ void mma16816(float* d, const uint32_t* a,
                                         uint32_t b0, uint32_t b1) {
    asm volatile("mma.sync.aligned.m16n8k16.row.col.f32.bf16.bf16.f32 "
                 "{%0,%1,%2,%3}, {%4,%5,%6,%7}, {%8,%9}, {%0,%1,%2,%3};"
                 : "+f"(d[0]), "+f"(d[1]), "+f"(d[2]), "+f"(d[3])
                 : "r"(a[0]), "r"(a[1]), "r"(a[2]), "r"(a[3]), "r"(b0), "r"(b1));
}

// ==================== fp32 -> (hi, lo) bf16 split ====================
__global__ void conv_split(const float* __restrict__ in,
                           __nv_bfloat16* __restrict__ hi,
                           __nv_bfloat16* __restrict__ lo, int n4) {
    int i = blockIdx.x * blockDim.x + threadIdx.x;
    if (i >= n4) return;
    float4 v = ((const float4*)in)[i];
    __nv_bfloat16 h0 = __float2bfloat16(v.x), h1 = __float2bfloat16(v.y);
    __nv_bfloat16 h2 = __float2bfloat16(v.z), h3 = __float2bfloat16(v.w);
    __nv_bfloat16 l0 = __float2bfloat16(v.x - __bfloat162float(h0));
    __nv_bfloat16 l1 = __float2bfloat16(v.y - __bfloat162float(h1));
    __nv_bfloat16 l2 = __float2bfloat16(v.z - __bfloat162float(h2));
    __nv_bfloat16 l3 = __float2bfloat16(v.w - __bfloat162float(h3));
    ((__nv_bfloat162*)hi)[2 * i + 0] = __nv_bfloat162(h0, h1);
    ((__nv_bfloat162*)hi)[2 * i + 1] = __nv_bfloat162(h2, h3);
    ((__nv_bfloat162*)lo)[2 * i + 0] = __nv_bfloat162(l0, l1);
    ((__nv_bfloat162*)lo)[2 * i + 1] = __nv_bfloat162(l2, l3);
}

// W [K=1024][N=1024] fp32 -> Wt hi/lo [N][K] bf16 (transpose + split)
__global__ void convT_split(const float* __restrict__ W,
                            __nv_bfloat16* __restrict__ hi,
                            __nv_bfloat16* __restrict__ lo) {
    __shared__ float t[32][33];
    int n0 = blockIdx.x * 32, k0 = blockIdx.y * 32;
    int tx = threadIdx.x, ty = threadIdx.y;
    #pragma unroll
    for (int i = 0; i < 4; i++)
        t[ty + 8 * i][tx] = W[(size_t)(k0 + ty + 8 * i) * 1024 + n0 + tx];
    __syncthreads();
    #pragma unroll
    for (int i = 0; i < 4; i++) {
        float a = t[tx][ty + 8 * i];
        __nv_bfloat16 h = __float2bfloat16(a);
        __nv_bfloat16 l = __float2bfloat16(a - __bfloat162float(h));
        size_t o = (size_t)(n0 + ty + 8 * i) * 1024 + k0 + tx;
        hi[o] = h; lo[o] = l;
    }
}

// ==================== warp-MMA split-bf16 GEMM ====================
// C[4096,1024] = A * W + bias (optional qmask row scale).
// A as (Ah, Al) row-major bf16 [4096][1024]; B as (Bh, Bl) = W^T [N=1024][K=1024].
// Tile 128x128x32, 8 warps (4x2), warp tile 32x64. 2-stage cp.async pipeline.
// Smem tile layout: [128 rows][32 k] bf16 with row stride 40 elems (80 B):
// 8 consecutive rows map to distinct 16B banks -> conflict-free ldmatrix.
#define TILE_B   10240               // 128 * 80
#define STAGE_B  40960               // 4 tiles

__global__ void __launch_bounds__(256, 2) tc_gemm(
    const __nv_bfloat16* __restrict__ Ah, const __nv_bfloat16* __restrict__ Al,
    const __nv_bfloat16* __restrict__ Bh, const __nv_bfloat16* __restrict__ Bl,
    const float* __restrict__ bias, const int* __restrict__ qmask,
    float* __restrict__ C, int applyQmask)
{
    extern __shared__ char smem[];
    const uint32_t sb = smem_u32(smem);

    const int tid = threadIdx.x, wid = tid >> 5, lane = tid & 31;
    const int m0 = blockIdx.y * 128, n0 = blockIdx.x * 128;
    const int warp_m = wid & 3, warp_n = wid >> 2;

    const __nv_bfloat16* srcs[4] = {
        Ah + (size_t)m0 * 1024, Al + (size_t)m0 * 1024,
        Bh + (size_t)n0 * 1024, Bl + (size_t)n0 * 1024 };

    // ldmatrix address mapping (shared by A and B):
    // lanes 0-7:(r0-7,chunk0) 8-15:(r8-15,chunk0) 16-23:(r0-7,chunk1) 24-31:(r8-15,chunk1)
    const int frow = ((lane >> 3) & 1) * 8 + (lane & 7);
    const int fchk = lane >> 4;
    const uint32_t aoff = (uint32_t)((warp_m * 32 + frow) * 80 + fchk * 16);
    const uint32_t boff = (uint32_t)((warp_n * 64 + frow) * 80 + fchk * 16);

    // per-thread load mapping: idx -> row idx>>2, 16B-chunk idx&3
    const int r_ld = tid >> 2, c_ld = tid & 3;

    float acc[2][8][4];
    #pragma unroll
    for (int mf = 0; mf < 2; mf++)
        #pragma unroll
        for (int nf = 0; nf < 8; nf++)
            #pragma unroll
            for (int e = 0; e < 4; e++) acc[mf][nf][e] = 0.0f;

    // ---- prefetch stage 0 ----
    #pragma unroll
    for (int t = 0; t < 4; t++) {
        #pragma unroll
        for (int i = 0; i < 2; i++) {
            int r = r_ld + i * 64;
            cp16(sb + t * TILE_B + r * 80 + c_ld * 16,
                 srcs[t] + (size_t)r * 1024 + c_ld * 8);
        }
    }
    CP_COMMIT();

    for (int ch = 0; ch < 32; ch++) {
        if (ch + 1 < 32) {
            const uint32_t dst = sb + ((ch + 1) & 1) * STAGE_B;
            const int k0 = (ch + 1) * 32;
            #pragma unroll
            for (int t = 0; t < 4; t++) {
                #pragma unroll
                for (int i = 0; i < 2; i++) {
                    int r = r_ld + i * 64;
                    cp16(dst + t * TILE_B + r * 80 + c_ld * 16,
                         srcs[t] + (size_t)r * 1024 + k0 + c_ld * 8);
                }
            }
            CP_COMMIT();
            asm volatile("cp.async.wait_group 1;" ::: "memory");
        } else {
            asm volatile("cp.async.wait_group 0;" ::: "memory");
        }
        __syncthreads();

        const uint32_t stage = sb + (ch & 1) * STAGE_B;
        // terms: (Ah,Bh), (Ah,Bl), (Al,Bh)
        #pragma unroll
        for (int term = 0; term < 3; term++) {
            const uint32_t sA = stage + (term == 2 ? TILE_B : 0u);
            const uint32_t sB = stage + 2u * TILE_B + (term == 1 ? TILE_B : 0u);
            #pragma unroll
            for (int ks = 0; ks < 2; ks++) {
                uint32_t a[2][4];
                ldsm4(a[0][0], a[0][1], a[0][2], a[0][3], sA + aoff + ks * 32);
                ldsm4(a[1][0], a[1][1], a[1][2], a[1][3], sA + aoff + 1280 + ks * 32);
                uint32_t b[4][4];
                #pragma unroll
                for (int nfp = 0; nfp < 4; nfp++)
                    ldsm4(b[nfp][0], b[nfp][1], b[nfp][2], b[nfp][3],
                          sB + boff + nfp * 1280 + ks * 32);
                #pragma unroll
                for (int mf = 0; mf < 2; mf++)
                    #pragma unroll
                    for (int nfp = 0; nfp < 4; nfp++) {
                        mma16816(acc[mf][2 * nfp],     a[mf], b[nfp][0], b[nfp][2]);
                        mma16816(acc[mf][2 * nfp + 1], a[mf], b[nfp][1], b[nfp][3]);
                    }
            }
        }
        __syncthreads();
    }

    // ---- epilogue ----
    const int rbase = m0 + warp_m * 32 + (lane >> 2);
    const int cbase = n0 + warp_n * 64 + (lane & 3) * 2;
    #pragma unroll
    for (int mf = 0; mf < 2; mf++) {
        #pragma unroll
        for (int h = 0; h < 2; h++) {
            int r = rbase + mf * 16 + h * 8;
            float qm = applyQmask ? (float)qmask[r] : 1.0f;
            #pragma unroll
            for (int nf = 0; nf < 8; nf++) {
                int cc = cbase + nf * 8;
                float2 o;
                o.x = (acc[mf][nf][2 * h + 0] + bias[cc])     * qm;
                o.y = (acc[mf][nf][2 * h + 1] + bias[cc + 1]) * qm;
                *(float2*)(C + (size_t)r * 1024 + cc) = o;
            }
        }
    }
}

// ==================== attention kernel (unchanged, correct) ====================
__global__ void __launch_bounds__(256) attn_kernel(
    const float* __restrict__ Qg, const float* __restrict__ Kg,
    const float* __restrict__ Vg, const int* __restrict__ vmask,
    float* __restrict__ Og)
{
    extern __shared__ float sm[];
    float* Qt     = sm;
    float* Kt     = Qt + 64 * 68;
    float* Vs     = Kt + 64 * 68;
    float* Sc     = Vs + 64 * 68;
    float* rowm   = Sc + 64 * 68;
    float* rowl   = rowm + 64;
    float* rowfac = rowl + 64;
    float* vmadd  = rowfac + 64;

    const int S = 1024, E = 1024;
    const int it  = blockIdx.x;
    const int bh  = blockIdx.y;
    const int b   = bh >> 4, h = bh & 15;
    const int tid = threadIdx.x;
    const int tx  = tid & 15, ty = tid >> 4;

    {
        int r0 = tid >> 4, d4 = tid & 15;
        const float* qbase = Qg + ((size_t)(b * S + it * 64)) * E + h * 64;
        #pragma unroll
        for (int p = 0; p < 4; p++) {
            int r = r0 + p * 16;
            float4 v = *(const float4*)(qbase + (size_t)r * E + d4 * 4);
            Qt[(d4 * 4 + 0) * 68 + r] = v.x;
            Qt[(d4 * 4 + 1) * 68 + r] = v.y;
            Qt[(d4 * 4 + 2) * 68 + r] = v.z;
            Qt[(d4 * 4 + 3) * 68 + r] = v.w;
        }
    }
    if (tid < 64) { rowm[tid] = -3.0e38f; rowl[tid] = 0.0f; }

    float oacc[4][4] = {};

    for (int jt = 0; jt < 16; jt++) {
        __syncthreads();
        {
            int r0 = tid >> 4, d4 = tid & 15;
            const float* kbase = Kg + ((size_t)(b * S + jt * 64)) * E + h * 64;
            const float* vbase = Vg + ((size_t)(b * S + jt * 64)) * E + h * 64;
            #pragma unroll
            for (int p = 0; p < 4; p++) {
                int r = r0 + p * 16;
                float4 kv = *(const float4*)(kbase + (size_t)r * E + d4 * 4);
                Kt[(d4 * 4 + 0) * 68 + r] = kv.x;
                Kt[(d4 * 4 + 1) * 68 + r] = kv.y;
                Kt[(d4 * 4 + 2) * 68 + r] = kv.z;
                Kt[(d4 * 4 + 3) * 68 + r] = kv.w;
                float4 vv = *(const float4*)(vbase + (size_t)r * E + d4 * 4);
                *(float4*)(&Vs[r * 68 + d4 * 4]) = vv;
            }
            if (tid < 64)
                vmadd[tid] = vmask[b * S + jt * 64 + tid] ? 0.0f : -1.0e12f;
        }
        __syncthreads();

        float sc[4][4] = {};
        #pragma unroll 4
        for (int kk = 0; kk < 64; kk++) {
            float ra[4], rb[4];
            #pragma unroll
            for (int i = 0; i < 4; i++) ra[i] = Qt[kk * 68 + ty * 4 + i];
            #pragma unroll
            for (int j = 0; j < 4; j++) rb[j] = Kt[kk * 68 + tx * 4 + j];
            #pragma unroll
            for (int i = 0; i < 4; i++)
                #pragma unroll
                for (int j = 0; j < 4; j++)
                    sc[i][j] += ra[i] * rb[j];
        }
        #pragma unroll
        for (int i = 0; i < 4; i++) {
            int gr = it * 64 + ty * 4 + i;
            #pragma unroll
            for (int j = 0; j < 4; j++) {
                int gc = jt * 64 + tx * 4 + j;
                float val = sc[i][j] * 0.125f + vmadd[tx * 4 + j];
                if (gc > gr) val += -1.0e12f;
                Sc[(ty * 4 + i) * 68 + tx * 4 + j] = val;
            }
        }
        __syncthreads();

        {
            int row = tid >> 2, sub = tid & 3;
            float lm = -3.0e38f;
            #pragma unroll
            for (int c = 0; c < 16; c++)
                lm = fmaxf(lm, Sc[row * 68 + sub * 16 + c]);
            lm = fmaxf(lm, __shfl_xor_sync(0xffffffffu, lm, 1));
            lm = fmaxf(lm, __shfl_xor_sync(0xffffffffu, lm, 2));
            float mold = rowm[row];
            float mnew = fmaxf(mold, lm);
            float ls = 0.0f;
            #pragma unroll
            for (int c = 0; c < 16; c++) {
                float p = __expf(Sc[row * 68 + sub * 16 + c] - mnew);
                Sc[row * 68 + sub * 16 + c] = p;
                ls += p;
            }
            ls += __shfl_xor_sync(0xffffffffu, ls, 1);
            ls += __shfl_xor_sync(0xffffffffu, ls, 2);
            if (sub == 0) {
                rowfac[row] = __expf(mold - mnew);
                rowl[row]   = rowl[row] * __expf(mold - mnew) + ls;
                rowm[row]   = mnew;
            }
        }
        __syncthreads();

        #pragma unroll
        for (int i = 0; i < 4; i++) {
            float f = rowfac[ty * 4 + i];
            #pragma unroll
            for (int j = 0; j < 4; j++) oacc[i][j] *= f;
        }
        #pragma unroll 4
        for (int kk = 0; kk < 64; kk++) {
            float pa[4], vb[4];
            #pragma unroll
            for (int i = 0; i < 4; i++) pa[i] = Sc[(ty * 4 + i) * 68 + kk];
            #pragma unroll
            for (int j = 0; j < 4; j++) vb[j] = Vs[kk * 68 + tx * 4 + j];
            #pragma unroll
            for (int i = 0; i < 4; i++)
                #pragma unroll
                for (int j = 0; j < 4; j++)
                    oacc[i][j] += pa[i] * vb[j];
        }
    }
    __syncthreads();

    #pragma unroll
    for (int i = 0; i < 4; i++) {
        int r = ty * 4 + i;
        float inv = 1.0f / rowl[r];
        size_t orow = ((size_t)(b * S + it * 64 + r)) * E + h * 64;
        #pragma unroll
        for (int j = 0; j < 4; j++)
            Og[orow + tx * 4 + j] = oacc[i][j] * inv;
    }
}

// ==================== launch ====================
extern "C" void kernel_launch(void* const* d_in, const int* in_sizes, int n_in,
                              void* d_out, int out_size)
{
    const float* q     = (const float*)d_in[0];
    const float* k     = (const float*)d_in[1];
    const float* v     = (const float*)d_in[2];
    const int*   vmask = (const int*)d_in[3];
    const int*   qmask = (const int*)d_in[4];
    const float* Wq = (const float*)d_in[6];
    const float* bq = (const float*)d_in[7];
    const float* Wk = (const float*)d_in[8];
    const float* bk = (const float*)d_in[9];
    const float* Wv = (const float*)d_in[10];
    const float* bv = (const float*)d_in[11];
    const float* Wo = (const float*)d_in[12];
    const float* bo = (const float*)d_in[13];
    float* out = (float*)d_out;

    float *qw, *kw, *vw, *att;
    cudaGetSymbolAddress((void**)&qw,  g_qw);
    cudaGetSymbolAddress((void**)&kw,  g_kw);
    cudaGetSymbolAddress((void**)&vw,  g_vw);
    cudaGetSymbolAddress((void**)&att, g_att);
    __nv_bfloat16 *qh, *ql, *kh, *kl, *vh, *vl, *ah, *al;
    __nv_bfloat16 *wqh, *wql, *wkh, *wkl, *wvh, *wvl, *woh, *wol;
    cudaGetSymbolAddress((void**)&qh, g_qh);  cudaGetSymbolAddress((void**)&ql, g_ql);
    cudaGetSymbolAddress((void**)&kh, g_kh);  cudaGetSymbolAddress((void**)&kl, g_kl);
    cudaGetSymbolAddress((void**)&vh, g_vh);  cudaGetSymbolAddress((void**)&vl, g_vl);
    cudaGetSymbolAddress((void**)&ah, g_ah);  cudaGetSymbolAddress((void**)&al, g_al);
    cudaGetSymbolAddress((void**)&wqh, g_wqh); cudaGetSymbolAddress((void**)&wql, g_wql);
    cudaGetSymbolAddress((void**)&wkh, g_wkh); cudaGetSymbolAddress((void**)&wkl, g_wkl);
    cudaGetSymbolAddress((void**)&wvh, g_wvh); cudaGetSymbolAddress((void**)&wvl, g_wvl);
    cudaGetSymbolAddress((void**)&woh, g_woh); cudaGetSymbolAddress((void**)&wol, g_wol);

    const int N4 = 4194304 / 4;
    conv_split<<<N4 / 256, 256>>>(q, qh, ql, N4);
    conv_split<<<N4 / 256, 256>>>(k, kh, kl, N4);
    conv_split<<<N4 / 256, 256>>>(v, vh, vl, N4);
    convT_split<<<dim3(32, 32), dim3(32, 8)>>>(Wq, wqh, wql);
    convT_split<<<dim3(32, 32), dim3(32, 8)>>>(Wk, wkh, wkl);
    convT_split<<<dim3(32, 32), dim3(32, 8)>>>(Wv, wvh, wvl);
    convT_split<<<dim3(32, 32), dim3(32, 8)>>>(Wo, woh, wol);

    const int GEMM_SMEM = 2 * STAGE_B;   // 81,920 B
    cudaFuncSetAttribute(tc_gemm, cudaFuncAttributeMaxDynamicSharedMemorySize, GEMM_SMEM);
    dim3 gg(8, 32);
    tc_gemm<<<gg, 256, GEMM_SMEM>>>(qh, ql, wqh, wql, bq, nullptr, qw, 0);
    tc_gemm<<<gg, 256, GEMM_SMEM>>>(kh, kl, wkh, wkl, bk, nullptr, kw, 0);
    tc_gemm<<<gg, 256, GEMM_SMEM>>>(vh, vl, wvh, wvl, bv, nullptr, vw, 0);

    const int ATTN_SMEM = (4 * 64 * 68 + 4 * 64) * (int)sizeof(float);
    cudaFuncSetAttribute(attn_kernel, cudaFuncAttributeMaxDynamicSharedMemorySize, ATTN_SMEM);
    attn_kernel<<<dim3(16, 64), 256, ATTN_SMEM>>>(qw, kw, vw, vmask, att);

    conv_split<<<N4 / 256, 256>>>(att, ah, al, N4);
    tc_gemm<<<gg, 256, GEMM_SMEM>>>(ah, al, woh, wol, bo, qmask, out, 1);
}

// round 6
// speedup vs baseline: 2.2679x; 1.5962x over previous
#include <cuda_runtime.h>
#include <cuda_bf16.h>
#include <cstdint>

// ==================== scratch (no cudaMalloc allowed) ====================
// input splits
__device__ __nv_bfloat16 g_xqh[4194304], g_xql[4194304];
__device__ __nv_bfloat16 g_xkh[4194304], g_xkl[4194304];
__device__ __nv_bfloat16 g_xvh[4194304], g_xvl[4194304];
// weight splits (transposed [N][K])
__device__ __nv_bfloat16 g_wqh[1048576], g_wql[1048576];
__device__ __nv_bfloat16 g_wkh[1048576], g_wkl[1048576];
__device__ __nv_bfloat16 g_wvh[1048576], g_wvl[1048576];
__device__ __nv_bfloat16 g_woh[1048576], g_wol[1048576];
// projection splits (GEMM outputs)
__device__ __nv_bfloat16 g_qh[4194304], g_ql[4194304];
__device__ __nv_bfloat16 g_kh[4194304], g_kl[4194304];
__device__ __nv_bfloat16 g_vh[4194304], g_vl[4194304];
// attention output split
__device__ __nv_bfloat16 g_ah[4194304], g_al[4194304];

// ==================== helpers ====================
__device__ __forceinline__ uint32_t smem_u32(const void* p) {
    uint32_t a;
    asm("{ .reg .u64 t; cvta.to.shared.u64 t, %1; cvt.u32.u64 %0, t; }"
        : "=r"(a) : "l"(p));
    return a;
}
__device__ __forceinline__ void cp16(uint32_t s, const void* g) {
    asm volatile("cp.async.cg.shared.global [%0], [%1], 16;" :: "r"(s), "l"(g));
}
#define CP_COMMIT() asm volatile("cp.async.commit_group;" ::: "memory")

__device__ __forceinline__ void ldsm4(uint32_t& r0, uint32_t& r1,
                                      uint32_t& r2, uint32_t& r3, uint32_t a) {
    asm volatile("ldmatrix.sync.aligned.m8n8.x4.shared.b16 {%0,%1,%2,%3}, [%4];"
                 : "=r"(r0), "=r"(r1), "=r"(r2), "=r"(r3) : "r"(a));
}
__device__ __forceinline__ void ldsm4t(uint32_t& r0, uint32_t& r1,
                                       uint32_t& r2, uint32_t& r3, uint32_t a) {
    asm volatile("ldmatrix.sync.aligned.m8n8.x4.trans.shared.b16 {%0,%1,%2,%3}, [%4];"
                 : "=r"(r0), "=r"(r1), "=r"(r2), "=r"(r3) : "r"(a));
}
__device__ __forceinline__ void mma16816(float* d, const uint32_t* a,
                                         uint32_t b0, uint32_t b1) {
    asm volatile("mma.sync.aligned.m16n8k16.row.col.f32.bf16.bf16.f32 "
                 "{%0,%1,%2,%3}, {%4,%5,%6,%7}, {%8,%9}, {%0,%1,%2,%3};"
                 : "+f"(d[0]), "+f"(d[1]), "+f"(d[2]), "+f"(d[3])
                 : "r"(a[0]), "r"(a[1]), "r"(a[2]), "r"(a[3]), "r"(b0), "r"(b1));
}
// pack {lo16 = x0, hi16 = x1}
__device__ __forceinline__ uint32_t packbf2(float x0, float x1) {
    uint32_t r;
    asm("cvt.rn.bf16x2.f32 %0, %1, %2;" : "=r"(r) : "f"(x1), "f"(x0));
    return r;
}

// ==================== fp32 -> (hi, lo) bf16 split ====================
__global__ void conv_split(const float* __restrict__ in,
                           __nv_bfloat16* __restrict__ hi,
                           __nv_bfloat16* __restrict__ lo, int n4) {
    int i = blockIdx.x * blockDim.x + threadIdx.x;
    if (i >= n4) return;
    float4 v = ((const float4*)in)[i];
    __nv_bfloat16 h0 = __float2bfloat16(v.x), h1 = __float2bfloat16(v.y);
    __nv_bfloat16 h2 = __float2bfloat16(v.z), h3 = __float2bfloat16(v.w);
    __nv_bfloat16 l0 = __float2bfloat16(v.x - __bfloat162float(h0));
    __nv_bfloat16 l1 = __float2bfloat16(v.y - __bfloat162float(h1));
    __nv_bfloat16 l2 = __float2bfloat16(v.z - __bfloat162float(h2));
    __nv_bfloat16 l3 = __float2bfloat16(v.w - __bfloat162float(h3));
    ((__nv_bfloat162*)hi)[2 * i + 0] = __nv_bfloat162(h0, h1);
    ((__nv_bfloat162*)hi)[2 * i + 1] = __nv_bfloat162(h2, h3);
    ((__nv_bfloat162*)lo)[2 * i + 0] = __nv_bfloat162(l0, l1);
    ((__nv_bfloat162*)lo)[2 * i + 1] = __nv_bfloat162(l2, l3);
}

// W [K=1024][N=1024] fp32 -> Wt hi/lo [N][K] bf16 (transpose + split)
__global__ void convT_split(const float* __restrict__ W,
                            __nv_bfloat16* __restrict__ hi,
                            __nv_bfloat16* __restrict__ lo) {
    __shared__ float t[32][33];
    int n0 = blockIdx.x * 32, k0 = blockIdx.y * 32;
    int tx = threadIdx.x, ty = threadIdx.y;
    #pragma unroll
    for (int i = 0; i < 4; i++)
        t[ty + 8 * i][tx] = W[(size_t)(k0 + ty + 8 * i) * 1024 + n0 + tx];
    __syncthreads();
    #pragma unroll
    for (int i = 0; i < 4; i++) {
        float a = t[tx][ty + 8 * i];
        __nv_bfloat16 h = __float2bfloat16(a);
        __nv_bfloat16 l = __float2bfloat16(a - __bfloat162float(h));
        size_t o = (size_t)(n0 + ty + 8 * i) * 1024 + k0 + tx;
        hi[o] = h; lo[o] = l;
    }
}

// ==================== warp-MMA split-bf16 GEMM ====================
// mode 0: C fp32; mode 1: C fp32 * qmask row; mode 2: split bf16 -> Ch, Cl
#define TILE_B   10240               // 128 * 80
#define STAGE_B  40960               // 4 tiles

__global__ void __launch_bounds__(256, 2) tc_gemm(
    const __nv_bfloat16* __restrict__ Ah, const __nv_bfloat16* __restrict__ Al,
    const __nv_bfloat16* __restrict__ Bh, const __nv_bfloat16* __restrict__ Bl,
    const float* __restrict__ bias, const int* __restrict__ qmask,
    float* __restrict__ C, __nv_bfloat16* __restrict__ Ch,
    __nv_bfloat16* __restrict__ Cl, int mode)
{
    extern __shared__ char smem[];
    const uint32_t sb = smem_u32(smem);

    const int tid = threadIdx.x, wid = tid >> 5, lane = tid & 31;
    const int m0 = blockIdx.y * 128, n0 = blockIdx.x * 128;
    const int warp_m = wid & 3, warp_n = wid >> 2;

    const __nv_bfloat16* srcs[4] = {
        Ah + (size_t)m0 * 1024, Al + (size_t)m0 * 1024,
        Bh + (size_t)n0 * 1024, Bl + (size_t)n0 * 1024 };

    const int frow = ((lane >> 3) & 1) * 8 + (lane & 7);
    const int fchk = lane >> 4;
    const uint32_t aoff = (uint32_t)((warp_m * 32 + frow) * 80 + fchk * 16);
    const uint32_t boff = (uint32_t)((warp_n * 64 + frow) * 80 + fchk * 16);
    const int r_ld = tid >> 2, c_ld = tid & 3;

    float acc[2][8][4];
    #pragma unroll
    for (int mf = 0; mf < 2; mf++)
        #pragma unroll
        for (int nf = 0; nf < 8; nf++)
            #pragma unroll
            for (int e = 0; e < 4; e++) acc[mf][nf][e] = 0.0f;

    #pragma unroll
    for (int t = 0; t < 4; t++)
        #pragma unroll
        for (int i = 0; i < 2; i++) {
            int r = r_ld + i * 64;
            cp16(sb + t * TILE_B + r * 80 + c_ld * 16,
                 srcs[t] + (size_t)r * 1024 + c_ld * 8);
        }
    CP_COMMIT();

    for (int ch = 0; ch < 32; ch++) {
        if (ch + 1 < 32) {
            const uint32_t dst = sb + ((ch + 1) & 1) * STAGE_B;
            const int k0 = (ch + 1) * 32;
            #pragma unroll
            for (int t = 0; t < 4; t++)
                #pragma unroll
                for (int i = 0; i < 2; i++) {
                    int r = r_ld + i * 64;
                    cp16(dst + t * TILE_B + r * 80 + c_ld * 16,
                         srcs[t] + (size_t)r * 1024 + k0 + c_ld * 8);
                }
            CP_COMMIT();
            asm volatile("cp.async.wait_group 1;" ::: "memory");
        } else {
            asm volatile("cp.async.wait_group 0;" ::: "memory");
        }
        __syncthreads();

        const uint32_t stage = sb + (ch & 1) * STAGE_B;
        #pragma unroll
        for (int term = 0; term < 3; term++) {
            const uint32_t sA = stage + (term == 2 ? TILE_B : 0u);
            const uint32_t sB = stage + 2u * TILE_B + (term == 1 ? TILE_B : 0u);
            #pragma unroll
            for (int ks = 0; ks < 2; ks++) {
                uint32_t a[2][4];
                ldsm4(a[0][0], a[0][1], a[0][2], a[0][3], sA + aoff + ks * 32);
                ldsm4(a[1][0], a[1][1], a[1][2], a[1][3], sA + aoff + 1280 + ks * 32);
                uint32_t b[4][4];
                #pragma unroll
                for (int nfp = 0; nfp < 4; nfp++)
                    ldsm4(b[nfp][0], b[nfp][1], b[nfp][2], b[nfp][3],
                          sB + boff + nfp * 1280 + ks * 32);
                #pragma unroll
                for (int mf = 0; mf < 2; mf++)
                    #pragma unroll
                    for (int nfp = 0; nfp < 4; nfp++) {
                        mma16816(acc[mf][2 * nfp],     a[mf], b[nfp][0], b[nfp][2]);
                        mma16816(acc[mf][2 * nfp + 1], a[mf], b[nfp][1], b[nfp][3]);
                    }
            }
        }
        __syncthreads();
    }

    // ---- epilogue ----
    const int rbase = m0 + warp_m * 32 + (lane >> 2);
    const int cbase = n0 + warp_n * 64 + (lane & 3) * 2;
    #pragma unroll
    for (int mf = 0; mf < 2; mf++)
        #pragma unroll
        for (int h = 0; h < 2; h++) {
            int r = rbase + mf * 16 + h * 8;
            float qm = (mode == 1) ? (float)qmask[r] : 1.0f;
            #pragma unroll
            for (int nf = 0; nf < 8; nf++) {
                int cc = cbase + nf * 8;
                float x = acc[mf][nf][2 * h + 0] + bias[cc];
                float y = acc[mf][nf][2 * h + 1] + bias[cc + 1];
                if (mode == 2) {
                    __nv_bfloat16 hx = __float2bfloat16(x);
                    __nv_bfloat16 hy = __float2bfloat16(y);
                    __nv_bfloat16 lx = __float2bfloat16(x - __bfloat162float(hx));
                    __nv_bfloat16 ly = __float2bfloat16(y - __bfloat162float(hy));
                    *(__nv_bfloat162*)(Ch + (size_t)r * 1024 + cc) = __nv_bfloat162(hx, hy);
                    *(__nv_bfloat162*)(Cl + (size_t)r * 1024 + cc) = __nv_bfloat162(lx, ly);
                } else {
                    float2 o; o.x = x * qm; o.y = y * qm;
                    *(float2*)(C + (size_t)r * 1024 + cc) = o;
                }
            }
        }
}

// ==================== tensor-core flash attention ====================
// grid (8 qtiles, 64 bh), 256 threads (8 warps x 16 rows). KV tiles of 128.
// smem: [Kh|Kl|Vh|Vl] x 2 stages, rows stride 72 elems (144B) -> conflict-free.
#define SST 72
#define STB (128 * SST * 2)          // 18432 B per tile

#define LOAD_KV(JT, S) do {                                                   \
    const int kv0_ = (JT) * 128;                                              \
    const __nv_bfloat16* mats_[4] = {                                         \
        Kh + ((size_t)(b * 1024 + kv0_)) * 1024 + headoff,                    \
        Kl + ((size_t)(b * 1024 + kv0_)) * 1024 + headoff,                    \
        Vh + ((size_t)(b * 1024 + kv0_)) * 1024 + headoff,                    \
        Vl + ((size_t)(b * 1024 + kv0_)) * 1024 + headoff };                  \
    uint32_t base_ = sb + (S) * 4 * STB;                                      \
    _Pragma("unroll")                                                         \
    for (int m_ = 0; m_ < 4; m_++)                                            \
        _Pragma("unroll")                                                     \
        for (int i_ = 0; i_ < 4; i_++) {                                      \
            int idx_ = tid + i_ * 256;                                        \
            int r_ = idx_ >> 3, ch_ = idx_ & 7;                               \
            cp16(base_ + m_ * STB + r_ * (SST * 2) + ch_ * 16,                \
                 mats_[m_] + (size_t)r_ * 1024 + ch_ * 8);                    \
        }                                                                     \
    if (tid < 128)                                                            \
        vmadd[(S) * 128 + tid] =                                              \
            vmask[b * 1024 + kv0_ + tid] ? 0.0f : -1.0e12f;                   \
    CP_COMMIT();                                                              \
} while (0)

__global__ void __launch_bounds__(256, 1) attn_tc(
    const __nv_bfloat16* __restrict__ Qh, const __nv_bfloat16* __restrict__ Ql,
    const __nv_bfloat16* __restrict__ Kh, const __nv_bfloat16* __restrict__ Kl,
    const __nv_bfloat16* __restrict__ Vh, const __nv_bfloat16* __restrict__ Vl,
    const int* __restrict__ vmask,
    __nv_bfloat16* __restrict__ Oh, __nv_bfloat16* __restrict__ Ol)
{
    extern __shared__ char smem[];
    const uint32_t sb = smem_u32(smem);
    float* vmadd = (float*)(smem + 8 * STB);   // [2][128]

    const int it = blockIdx.x, bh = blockIdx.y;
    const int b = bh >> 4, h = bh & 15;
    const int tid = threadIdx.x, wid = tid >> 5, lane = tid & 31;
    const int g = lane >> 2, tg = lane & 3;
    const size_t headoff = (size_t)h * 64;
    const int qrow0 = it * 128;
    const int frow = lane & 15, fchk = lane >> 4;

    // ---- stage Q (hi/lo) into stage-0 K slots, load A-frags to regs ----
    #pragma unroll
    for (int m = 0; m < 2; m++) {
        const __nv_bfloat16* src =
            (m ? Ql : Qh) + ((size_t)(b * 1024 + qrow0)) * 1024 + headoff;
        uint32_t dstb = sb + m * STB;
        #pragma unroll
        for (int i = 0; i < 4; i++) {
            int idx = tid + i * 256;
            int r = idx >> 3, ch = idx & 7;
            cp16(dstb + r * (SST * 2) + ch * 16, src + (size_t)r * 1024 + ch * 8);
        }
    }
    CP_COMMIT();
    asm volatile("cp.async.wait_group 0;" ::: "memory");
    __syncthreads();

    uint32_t qfh[4][4], qfl[4][4];
    {
        uint32_t abase = sb + (wid * 16 + frow) * (SST * 2) + fchk * 16;
        #pragma unroll
        for (int ks = 0; ks < 4; ks++) {
            ldsm4(qfh[ks][0], qfh[ks][1], qfh[ks][2], qfh[ks][3], abase + ks * 32);
            ldsm4(qfl[ks][0], qfl[ks][1], qfl[ks][2], qfl[ks][3],
                  abase + STB + ks * 32);
        }
    }
    __syncthreads();

    float oacc[8][4];
    #pragma unroll
    for (int nf = 0; nf < 8; nf++)
        #pragma unroll
        for (int e = 0; e < 4; e++) oacc[nf][e] = 0.0f;
    float m0r = -3.0e38f, m1r = -3.0e38f, l0r = 0.0f, l1r = 0.0f;

    LOAD_KV(0, 0);

    for (int jt = 0; jt < 8; jt++) {
        if (jt > 0) __syncthreads();
        if (jt < 7) {
            LOAD_KV(jt + 1, (jt + 1) & 1);
            asm volatile("cp.async.wait_group 1;" ::: "memory");
        } else {
            asm volatile("cp.async.wait_group 0;" ::: "memory");
        }
        __syncthreads();

        const int s = jt & 1;
        const int kv0 = jt * 128;
        const float* vm_s = vmadd + s * 128;
        const uint32_t khb = sb + s * 4 * STB;
        const uint32_t vhb = khb + 2 * STB;

        // ---- scores: 3-term split mma ----
        float sacc[16][4];
        #pragma unroll
        for (int nf = 0; nf < 16; nf++)
            #pragma unroll
            for (int e = 0; e < 4; e++) sacc[nf][e] = 0.0f;

        const uint32_t kaddr = khb + frow * (SST * 2) + fchk * 16;
        #pragma unroll
        for (int ks = 0; ks < 4; ks++)
            #pragma unroll
            for (int nfp = 0; nfp < 8; nfp++) {
                uint32_t off = (uint32_t)(nfp * 16) * (SST * 2) + ks * 32;
                uint32_t b0, b1, b2, b3;
                ldsm4(b0, b1, b2, b3, kaddr + off);
                mma16816(sacc[2 * nfp],     qfh[ks], b0, b2);
                mma16816(sacc[2 * nfp + 1], qfh[ks], b1, b3);
                mma16816(sacc[2 * nfp],     qfl[ks], b0, b2);
                mma16816(sacc[2 * nfp + 1], qfl[ks], b1, b3);
                uint32_t c0, c1, c2, c3;
                ldsm4(c0, c1, c2, c3, kaddr + off + STB);
                mma16816(sacc[2 * nfp],     qfh[ks], c0, c2);
                mma16816(sacc[2 * nfp + 1], qfh[ks], c1, c3);
            }

        // ---- masks ----
        const int gr0 = qrow0 + wid * 16 + g, gr1 = gr0 + 8;
        #pragma unroll
        for (int nf = 0; nf < 16; nf++) {
            int c0 = nf * 8 + tg * 2;
            int gc0 = kv0 + c0, gc1 = gc0 + 1;
            float vm0 = vm_s[c0], vm1 = vm_s[c0 + 1];
            sacc[nf][0] = sacc[nf][0] * 0.125f + vm0 + (gc0 > gr0 ? -1.0e12f : 0.0f);
            sacc[nf][1] = sacc[nf][1] * 0.125f + vm1 + (gc1 > gr0 ? -1.0e12f : 0.0f);
            sacc[nf][2] = sacc[nf][2] * 0.125f + vm0 + (gc0 > gr1 ? -1.0e12f : 0.0f);
            sacc[nf][3] = sacc[nf][3] * 0.125f + vm1 + (gc1 > gr1 ? -1.0e12f : 0.0f);
        }

        // ---- online softmax (rows within one quad) ----
        float tm0 = -3.0e38f, tm1 = -3.0e38f;
        #pragma unroll
        for (int nf = 0; nf < 16; nf++) {
            tm0 = fmaxf(tm0, fmaxf(sacc[nf][0], sacc[nf][1]));
            tm1 = fmaxf(tm1, fmaxf(sacc[nf][2], sacc[nf][3]));
        }
        tm0 = fmaxf(tm0, __shfl_xor_sync(0xffffffffu, tm0, 1));
        tm0 = fmaxf(tm0, __shfl_xor_sync(0xffffffffu, tm0, 2));
        tm1 = fmaxf(tm1, __shfl_xor_sync(0xffffffffu, tm1, 1));
        tm1 = fmaxf(tm1, __shfl_xor_sync(0xffffffffu, tm1, 2));
        const float mn0 = fmaxf(m0r, tm0), mn1 = fmaxf(m1r, tm1);
        const float sc0 = __expf(m0r - mn0), sc1 = __expf(m1r - mn1);
        float ls0 = 0.0f, ls1 = 0.0f;
        #pragma unroll
        for (int nf = 0; nf < 16; nf++) {
            sacc[nf][0] = __expf(sacc[nf][0] - mn0); ls0 += sacc[nf][0];
            sacc[nf][1] = __expf(sacc[nf][1] - mn0); ls0 += sacc[nf][1];
            sacc[nf][2] = __expf(sacc[nf][2] - mn1); ls1 += sacc[nf][2];
            sacc[nf][3] = __expf(sacc[nf][3] - mn1); ls1 += sacc[nf][3];
        }
        ls0 += __shfl_xor_sync(0xffffffffu, ls0, 1);
        ls0 += __shfl_xor_sync(0xffffffffu, ls0, 2);
        ls1 += __shfl_xor_sync(0xffffffffu, ls1, 1);
        ls1 += __shfl_xor_sync(0xffffffffu, ls1, 2);
        l0r = l0r * sc0 + ls0;  l1r = l1r * sc1 + ls1;
        m0r = mn0;  m1r = mn1;
        #pragma unroll
        for (int nf = 0; nf < 8; nf++) {
            oacc[nf][0] *= sc0; oacc[nf][1] *= sc0;
            oacc[nf][2] *= sc1; oacc[nf][3] *= sc1;
        }

        // ---- P*V: acc regs become A-frags (split P), V via ldmatrix.trans ----
        const uint32_t vtb = vhb +
            (uint32_t)(((lane >> 3) & 1) * 8 + (lane & 7)) * (SST * 2) +
            (lane >> 4) * 16;
        #pragma unroll
        for (int kc = 0; kc < 8; kc++) {
            uint32_t AH[4], AL[4];
            #pragma unroll
            for (int half = 0; half < 2; half++) {
                const float* sp = sacc[2 * kc + half];
                uint32_t h0 = packbf2(sp[0], sp[1]);
                uint32_t h1 = packbf2(sp[2], sp[3]);
                AH[2 * half + 0] = h0;  AH[2 * half + 1] = h1;
                __nv_bfloat162 hv0 = *(__nv_bfloat162*)&h0;
                __nv_bfloat162 hv1 = *(__nv_bfloat162*)&h1;
                AL[2 * half + 0] = packbf2(sp[0] - __bfloat162float(hv0.x),
                                           sp[1] - __bfloat162float(hv0.y));
                AL[2 * half + 1] = packbf2(sp[2] - __bfloat162float(hv1.x),
                                           sp[3] - __bfloat162float(hv1.y));
            }
            const uint32_t vrow = vtb + (uint32_t)(kc * 16) * (SST * 2);
            #pragma unroll
            for (int nfp = 0; nfp < 4; nfp++) {
                uint32_t r0, r1, r2, r3;
                ldsm4t(r0, r1, r2, r3, vrow + nfp * 32);
                mma16816(oacc[2 * nfp],     AH, r0, r1);
                mma16816(oacc[2 * nfp + 1], AH, r2, r3);
                mma16816(oacc[2 * nfp],     AL, r0, r1);
                mma16816(oacc[2 * nfp + 1], AL, r2, r3);
                uint32_t c0, c1, c2, c3;
                ldsm4t(c0, c1, c2, c3, vrow + STB + nfp * 32);
                mma16816(oacc[2 * nfp],     AH, c0, c1);
                mma16816(oacc[2 * nfp + 1], AH, c2, c3);
            }
        }
    }

    // ---- epilogue: O = oacc / l, write split bf16 ----
    const float inv0 = 1.0f / l0r, inv1 = 1.0f / l1r;
    const int r0g = qrow0 + wid * 16 + g, r1g = r0g + 8;
    const size_t o0 = ((size_t)(b * 1024 + r0g)) * 1024 + headoff;
    const size_t o1 = ((size_t)(b * 1024 + r1g)) * 1024 + headoff;
    #pragma unroll
    for (int nf = 0; nf < 8; nf++) {
        int c = nf * 8 + tg * 2;
        float x = oacc[nf][0] * inv0, y = oacc[nf][1] * inv0;
        __nv_bfloat16 hx = __float2bfloat16(x), hy = __float2bfloat16(y);
        *(__nv_bfloat162*)(Oh + o0 + c) = __nv_bfloat162(hx, hy);
        *(__nv_bfloat162*)(Ol + o0 + c) = __nv_bfloat162(
            __float2bfloat16(x - __bfloat162float(hx)),
            __float2bfloat16(y - __bfloat162float(hy)));
        x = oacc[nf][2] * inv1; y = oacc[nf][3] * inv1;
        hx = __float2bfloat16(x); hy = __float2bfloat16(y);
        *(__nv_bfloat162*)(Oh + o1 + c) = __nv_bfloat162(hx, hy);
        *(__nv_bfloat162*)(Ol + o1 + c) = __nv_bfloat162(
            __float2bfloat16(x - __bfloat162float(hx)),
            __float2bfloat16(y - __bfloat162float(hy)));
    }
}

// ==================== launch ====================
extern "C" void kernel_launch(void* const* d_in, const int* in_sizes, int n_in,
                              void* d_out, int out_size)
{
    const float* q     = (const float*)d_in[0];
    const float* k     = (const float*)d_in[1];
    const float* v     = (const float*)d_in[2];
    const int*   vmask = (const int*)d_in[3];
    const int*   qmask = (const int*)d_in[4];
    const float* Wq = (const float*)d_in[6];
    const float* bq = (const float*)d_in[7];
    const float* Wk = (const float*)d_in[8];
    const float* bk = (const float*)d_in[9];
    const float* Wv = (const float*)d_in[10];
    const float* bv = (const float*)d_in[11];
    const float* Wo = (const float*)d_in[12];
    const float* bo = (const float*)d_in[13];
    float* out = (float*)d_out;

    __nv_bfloat16 *xqh, *xql, *xkh, *xkl, *xvh, *xvl;
    __nv_bfloat16 *wqh, *wql, *wkh, *wkl, *wvh, *wvl, *woh, *wol;
    __nv_bfloat16 *qh, *ql, *kh, *kl, *vh, *vl, *ah, *al;
    cudaGetSymbolAddress((void**)&xqh, g_xqh); cudaGetSymbolAddress((void**)&xql, g_xql);
    cudaGetSymbolAddress((void**)&xkh, g_xkh); cudaGetSymbolAddress((void**)&xkl, g_xkl);
    cudaGetSymbolAddress((void**)&xvh, g_xvh); cudaGetSymbolAddress((void**)&xvl, g_xvl);
    cudaGetSymbolAddress((void**)&wqh, g_wqh); cudaGetSymbolAddress((void**)&wql, g_wql);
    cudaGetSymbolAddress((void**)&wkh, g_wkh); cudaGetSymbolAddress((void**)&wkl, g_wkl);
    cudaGetSymbolAddress((void**)&wvh, g_wvh); cudaGetSymbolAddress((void**)&wvl, g_wvl);
    cudaGetSymbolAddress((void**)&woh, g_woh); cudaGetSymbolAddress((void**)&wol, g_wol);
    cudaGetSymbolAddress((void**)&qh, g_qh);   cudaGetSymbolAddress((void**)&ql, g_ql);
    cudaGetSymbolAddress((void**)&kh, g_kh);   cudaGetSymbolAddress((void**)&kl, g_kl);
    cudaGetSymbolAddress((void**)&vh, g_vh);   cudaGetSymbolAddress((void**)&vl, g_vl);
    cudaGetSymbolAddress((void**)&ah, g_ah);   cudaGetSymbolAddress((void**)&al, g_al);

    const int N4 = 4194304 / 4;
    conv_split<<<N4 / 256, 256>>>(q, xqh, xql, N4);
    conv_split<<<N4 / 256, 256>>>(k, xkh, xkl, N4);
    conv_split<<<N4 / 256, 256>>>(v, xvh, xvl, N4);
    convT_split<<<dim3(32, 32), dim3(32, 8)>>>(Wq, wqh, wql);
    convT_split<<<dim3(32, 32), dim3(32, 8)>>>(Wk, wkh, wkl);
    convT_split<<<dim3(32, 32), dim3(32, 8)>>>(Wv, wvh, wvl);
    convT_split<<<dim3(32, 32), dim3(32, 8)>>>(Wo, woh, wol);

    const int GEMM_SMEM = 2 * STAGE_B;   // 81,920 B
    cudaFuncSetAttribute(tc_gemm, cudaFuncAttributeMaxDynamicSharedMemorySize, GEMM_SMEM);
    dim3 gg(8, 32);
    tc_gemm<<<gg, 256, GEMM_SMEM>>>(xqh, xql, wqh, wql, bq, nullptr,
                                    nullptr, qh, ql, 2);
    tc_gemm<<<gg, 256, GEMM_SMEM>>>(xkh, xkl, wkh, wkl, bk, nullptr,
                                    nullptr, kh, kl, 2);
    tc_gemm<<<gg, 256, GEMM_SMEM>>>(xvh, xvl, wvh, wvl, bv, nullptr,
                                    nullptr, vh, vl, 2);

    const int ATTN_SMEM = 8 * STB + 2 * 128 * (int)sizeof(float);  // 148,480 B
    cudaFuncSetAttribute(attn_tc, cudaFuncAttributeMaxDynamicSharedMemorySize, ATTN_SMEM);
    attn_tc<<<dim3(8, 64), 256, ATTN_SMEM>>>(qh, ql, kh, kl, vh, vl, vmask, ah, al);

    tc_gemm<<<gg, 256, GEMM_SMEM>>>(ah, al, woh, wol, bo, qmask,
                                    out, nullptr, nullptr, 1);
}